// round 9
// baseline (speedup 1.0000x reference)
#include <cuda_runtime.h>
#include <cuda_fp16.h>
#include <cstdint>
#include <cstddef>

#define MDIM 16
#define KDIM 8192
#define NDIM 8192
#define KSPLIT 16
#define KPER 512               // k per split
#define NGRP 4                 // 128-k groups per split
#define NT 16                  // n tiles (512 n each)
#define THREADS 256
#define N8W 8                  // n8 blocks per warp

// smem: frags [32 blocks][32 lanes] uint4, then 2 qweight stage buffers
#define ROWSTRIDE 80           // 64B data + 16B pad (bank-conflict-free: 20j % 32 distinct)
#define STAGE_BYTES (512 * ROWSTRIDE)        // 40960
#define SM_FRAG 0                             // 16384 B
#define SM_STAGE 16384
#define SM_TOTAL (16384 + 2 * STAGE_BYTES)   // 98304 B -> 2 CTAs/SM

__device__ __align__(16) float g_partial[KSPLIT][1024][128];   // 8 MB

__device__ __forceinline__ uint32_t smem_u32(const void* p) {
    uint32_t a;
    asm("{ .reg .u64 t; cvta.to.shared.u64 t, %1; cvt.u32.u64 %0, t; }" : "=r"(a) : "l"(p));
    return a;
}

#define CP_ASYNC16(dst, src) \
    asm volatile("cp.async.cg.shared.global [%0], [%1], 16;" \
                 :: "r"((uint32_t)(dst)), "l"(src))
#define CP_COMMIT() asm volatile("cp.async.commit_group;" ::: "memory")
#define CP_WAIT(n) asm volatile("cp.async.wait_group %0;" :: "n"(n) : "memory")

__device__ __forceinline__ void mma16816(float4& c,
                                         uint32_t a0, uint32_t a1, uint32_t a2, uint32_t a3,
                                         uint32_t b0, uint32_t b1) {
    asm volatile(
        "mma.sync.aligned.m16n8k16.row.col.f32.f16.f16.f32 "
        "{%0,%1,%2,%3},{%4,%5,%6,%7},{%8,%9},{%0,%1,%2,%3};"
        : "+f"(c.x), "+f"(c.y), "+f"(c.z), "+f"(c.w)
        : "r"(a0), "r"(a1), "r"(a2), "r"(a3), "r"(b0), "r"(b1));
}

// one int32 (8 nibbles) -> half2 {q[c], q[c+4]} * s + z  (bias removed exactly)
__device__ __forceinline__ uint32_t dq2(uint32_t w, uint32_t c4, __half2 s2, __half2 z2) {
    uint32_t t = ((w >> c4) & 0x000F000Fu) | 0x64006400u;
    uint32_t bu = 0x64006400u;
    __half2 q = __hsub2(*reinterpret_cast<__half2*>(&t), *reinterpret_cast<__half2*>(&bu));
    __half2 r = __hfma2(q, s2, z2);
    return *reinterpret_cast<uint32_t*>(&r);
}

__global__ void __launch_bounds__(THREADS, 2) wq_gemm(
    const float* __restrict__ x, const int* __restrict__ qw,
    const float* __restrict__ scales, const float* __restrict__ zeros) {
    extern __shared__ char smem[];
    uint4* frag = reinterpret_cast<uint4*>(smem + SM_FRAG);
    const int tid = threadIdx.x;
    const int nt = blockIdx.x & (NT - 1);
    const int ks = blockIdx.x >> 4;

    const uint32_t stage0 = smem_u32(smem + SM_STAGE);
    // qweight base for this CTA: rows nt*512.., k-offset ks*256 bytes
    const char* qwb = reinterpret_cast<const char*>(qw) +
                      (size_t)(nt * 512) * 4096 + (size_t)ks * 256;

    // ---- issue cp.async stages for g=0 and g=1 (2048 x 16B chunks each) ----
#pragma unroll
    for (int gg = 0; gg < 2; gg++) {
#pragma unroll
        for (int j = 0; j < 8; j++) {
            int lin = tid + j * THREADS;      // 0..2047
            int r = lin >> 2, q16 = lin & 3;
            CP_ASYNC16(stage0 + (uint32_t)gg * STAGE_BYTES + (uint32_t)(r * ROWSTRIDE + q16 * 16),
                       qwb + (size_t)r * 4096 + gg * 64 + q16 * 16);
        }
        CP_COMMIT();
    }

    // ---- pack x A-fragments straight from gmem (overlaps cp.async latency) ----
    // virtual-k permutation: 2c <-> c, 2c+1 <-> c+4
#pragma unroll
    for (int j = 0; j < 4; j++) {
        int e = tid + j * THREADS;            // 0..1023 = (block, lane)
        int b = e >> 5, l = e & 31;
        int r = l >> 2, c = l & 3;
        const float* r0 = x + (size_t)r * KDIM + ks * KPER + b * 16;
        const float* r1 = x + (size_t)(r + 8) * KDIM + ks * KPER + b * 16;
        __half2 a0 = __floats2half2_rn(r0[c], r0[c + 4]);
        __half2 a1 = __floats2half2_rn(r1[c], r1[c + 4]);
        __half2 a2 = __floats2half2_rn(r0[8 + c], r0[12 + c]);
        __half2 a3 = __floats2half2_rn(r1[8 + c], r1[12 + c]);
        uint4 f;
        f.x = *reinterpret_cast<uint32_t*>(&a0);
        f.y = *reinterpret_cast<uint32_t*>(&a1);
        f.z = *reinterpret_cast<uint32_t*>(&a2);
        f.w = *reinterpret_cast<uint32_t*>(&a3);
        frag[e] = f;
    }

    // ---- main loop ----
    const int wid = tid >> 5, lane = tid & 31;
    const int nb0 = nt * 64 + wid * N8W;
    const int r_in8 = lane >> 2;
    const uint32_t c4 = (uint32_t)(lane & 3) * 4;
    const int row0 = nb0 * 8 + r_in8;
    const int lrow0 = wid * 64 + r_in8;       // CTA-local staged row

    float4 acc[N8W];
#pragma unroll
    for (int i = 0; i < N8W; i++) acc[i] = make_float4(0.f, 0.f, 0.f, 0.f);

#pragma unroll 1
    for (int g = 0; g < NGRP; g++) {
        if (g == NGRP - 1) CP_WAIT(0); else CP_WAIT(1);
        __syncthreads();

        __half2 s2[N8W], z2[N8W];
        const float* sp = scales + (size_t)(ks * NGRP + g) * NDIM + row0;
        const float* zp = zeros + (size_t)(ks * NGRP + g) * NDIM + row0;
#pragma unroll
        for (int i = 0; i < N8W; i++) {
            s2[i] = __half2half2(__float2half_rn(sp[i * 8]));
            z2[i] = __half2half2(__float2half_rn(zp[i * 8]));
        }

        const char* sbase = smem + SM_STAGE + (size_t)(g & 1) * STAGE_BYTES;
#pragma unroll
        for (int p = 0; p < 4; p++) {
            uint4 ah0 = frag[((g * 8 + p * 2 + 0) << 5) + lane];
            uint4 ah1 = frag[((g * 8 + p * 2 + 1) << 5) + lane];
#pragma unroll
            for (int i = 0; i < N8W; i++) {
                uint4 w = *reinterpret_cast<const uint4*>(
                    sbase + (size_t)(lrow0 + i * 8) * ROWSTRIDE + p * 16);
                uint32_t b0 = dq2(w.x, c4, s2[i], z2[i]);
                uint32_t b1 = dq2(w.y, c4, s2[i], z2[i]);
                mma16816(acc[i], ah0.x, ah0.y, ah0.z, ah0.w, b0, b1);
                b0 = dq2(w.z, c4, s2[i], z2[i]);
                b1 = dq2(w.w, c4, s2[i], z2[i]);
                mma16816(acc[i], ah1.x, ah1.y, ah1.z, ah1.w, b0, b1);
            }
        }

        __syncthreads();
        if (g + 2 < NGRP) {
            uint32_t dstbuf = stage0 + (uint32_t)(g & 1) * STAGE_BYTES;
#pragma unroll
            for (int j = 0; j < 8; j++) {
                int lin = tid + j * THREADS;
                int r = lin >> 2, q16 = lin & 3;
                CP_ASYNC16(dstbuf + (uint32_t)(r * ROWSTRIDE + q16 * 16),
                           qwb + (size_t)r * 4096 + (g + 2) * 64 + q16 * 16);
            }
            CP_COMMIT();
        }
    }

    // ---- store partials ----
    const int off = r_in8 * 8 + (lane & 3) * 2;
#pragma unroll
    for (int i = 0; i < N8W; i++) {
        float* pb = &g_partial[ks][nb0 + i][0];
        *reinterpret_cast<float2*>(pb + off) = make_float2(acc[i].x, acc[i].y);
        *reinterpret_cast<float2*>(pb + 64 + off) = make_float2(acc[i].z, acc[i].w);
    }
}

// combine: thread mapping matches partial layout -> fully coalesced reads
__global__ void __launch_bounds__(256) wq_combine(const float* __restrict__ bias,
                                                  float* __restrict__ out) {
    int idx = blockIdx.x * 256 + threadIdx.x;   // 0..131071
    int nb = idx >> 7;                          // n8 block
    int off = idx & 127;                        // m*8 + nc
    float acc = 0.f;
#pragma unroll
    for (int ks = 0; ks < KSPLIT; ks++) acc += g_partial[ks][nb][off];
    int m = off >> 3, nc = off & 7;
    int n = nb * 8 + nc;
    out[(size_t)m * NDIM + n] = acc + bias[n];
}

extern "C" void kernel_launch(void* const* d_in, const int* in_sizes, int n_in,
                              void* d_out, int out_size) {
    const float* x = (const float*)d_in[0];
    const int* qw = (const int*)d_in[1];
    const float* sc = (const float*)d_in[2];
    const float* zz = (const float*)d_in[3];
    const float* bias = (const float*)d_in[4];
    (void)in_sizes; (void)n_in; (void)out_size;

    cudaFuncSetAttribute(wq_gemm, cudaFuncAttributeMaxDynamicSharedMemorySize, SM_TOTAL);
    wq_gemm<<<NT * KSPLIT, THREADS, SM_TOTAL>>>(x, qw, sc, zz);
    wq_combine<<<(MDIM * NDIM) / 256, 256>>>(bias, (float*)d_out);
}